// round 1
// baseline (speedup 1.0000x reference)
#include <cuda_runtime.h>
#include <cuda_bf16.h>
#include <math.h>

// ---------------- problem constants ----------------
#define Bsz   64
#define Nn    256
#define CT    3
#define HID   256
#define HEADS 4
#define Ch    64          // per-head channels
#define Eg    8192
#define F_IN  (Nn*CT)     // 768
#define ROWS  (Bsz*Nn)    // 16384
#define NEGS  0.2f
#define EPSBN 1e-5f

// ---------------- scratch (device globals, no allocs) ----------------
__device__ float g_h [ROWS*HID];
__device__ float g_xl[ROWS*HID];
__device__ float g_xr[ROWS*HID];
__device__ float g_h2[ROWS*HID];
__device__ float g_pool[Bsz*HID];
__device__ int   g_off[Nn+1];
__device__ int   g_eid[Eg];

__device__ __forceinline__ float gelu_exact(float x) {
    return x * normcdff(x);   // x * Phi(x) == 0.5*x*(1+erf(x/sqrt(2)))
}

// ---------------- deterministic CSR build (1 block, 256 threads) ----------------
__global__ void build_csr_kernel(const int* __restrict__ ei,
                                 int* __restrict__ off, int* __restrict__ eid) {
    const int n = threadIdx.x;                 // node id
    const int* dst = ei + Eg;
    int cnt = 0;
    for (int e = 0; e < Eg; e++) cnt += (dst[e] == n);
    __shared__ int s_cnt[Nn];
    __shared__ int s_off[Nn+1];
    s_cnt[n] = cnt;
    __syncthreads();
    if (n == 0) {
        s_off[0] = 0;
        for (int i = 0; i < Nn; i++) s_off[i+1] = s_off[i] + s_cnt[i];
    }
    __syncthreads();
    off[n] = s_off[n];
    if (n == 0) off[Nn] = s_off[Nn];
    int w = s_off[n];
    for (int e = 0; e < Eg; e++)
        if (dst[e] == n) eid[w++] = e;         // ordered by e -> deterministic
}

// ---------------- SGEMM: C[M,N] = A[M,K] @ B[K,N] (+bias) (+BN+gelu) ----------------
// 128x128x8 tile, 256 threads, 8x8 microtile
// epi: 0 -> C = AB + bias ; 1 -> C = gelu(BN(AB + bias))
__global__ __launch_bounds__(256)
void sgemm_kernel(const float* __restrict__ A, const float* __restrict__ B,
                  int M, int N, int K,
                  const float* __restrict__ bias,
                  const float* __restrict__ gam, const float* __restrict__ bet,
                  const float* __restrict__ mu,  const float* __restrict__ var,
                  int epi, float* __restrict__ C)
{
    __shared__ float As[8][128];
    __shared__ float Bs[8][128];

    const int tid = threadIdx.x;
    const int cb  = blockIdx.x * 128;
    const int rb  = blockIdx.y * 128;

    const int ar  = tid >> 1;           // 0..127 : A tile row
    const int ac  = (tid & 1) * 4;      // 0/4    : A tile col (float4)
    const int br  = tid >> 5;           // 0..7   : B tile row
    const int bc  = (tid & 31) * 4;     // 0..124 : B tile col (float4)
    const int tx  = tid & 15;
    const int ty  = tid >> 4;

    float acc[8][8];
#pragma unroll
    for (int i = 0; i < 8; i++)
#pragma unroll
        for (int j = 0; j < 8; j++) acc[i][j] = 0.f;

    const float* Ap = A + (size_t)(rb + ar) * K + ac;
    const float* Bp = B + (size_t)br * N + cb + bc;

    for (int kt = 0; kt < K; kt += 8) {
        float4 av = *(const float4*)(Ap + kt);
        As[ac+0][ar] = av.x; As[ac+1][ar] = av.y;
        As[ac+2][ar] = av.z; As[ac+3][ar] = av.w;
        float4 bv = *(const float4*)(Bp + (size_t)kt * N);
        *(float4*)&Bs[br][bc] = bv;
        __syncthreads();
#pragma unroll
        for (int kk = 0; kk < 8; kk++) {
            float a[8], b[8];
            *(float4*)&a[0] = *(const float4*)&As[kk][ty*8];
            *(float4*)&a[4] = *(const float4*)&As[kk][ty*8+4];
            *(float4*)&b[0] = *(const float4*)&Bs[kk][tx*8];
            *(float4*)&b[4] = *(const float4*)&Bs[kk][tx*8+4];
#pragma unroll
            for (int i = 0; i < 8; i++)
#pragma unroll
                for (int j = 0; j < 8; j++) acc[i][j] = fmaf(a[i], b[j], acc[i][j]);
        }
        __syncthreads();
    }

    const int row0 = rb + ty * 8;
    const int col0 = cb + tx * 8;
    float pb[8], pscale[8], pshift[8];
#pragma unroll
    for (int j = 0; j < 8; j++) pb[j] = bias[col0 + j];
    if (epi == 1) {
#pragma unroll
        for (int j = 0; j < 8; j++) {
            float inv = rsqrtf(var[col0 + j] + EPSBN);
            pscale[j] = gam[col0 + j] * inv;
            pshift[j] = bet[col0 + j] - mu[col0 + j] * pscale[j];
        }
    }
#pragma unroll
    for (int i = 0; i < 8; i++) {
        float o[8];
#pragma unroll
        for (int j = 0; j < 8; j++) {
            float v = acc[i][j] + pb[j];
            if (epi == 1) {
                v = v * pscale[j] + pshift[j];
                v = gelu_exact(v);
            }
            o[j] = v;
        }
        float* cp = C + (size_t)(row0 + i) * N + col0;
        *(float4*)(cp)     = *(float4*)&o[0];
        *(float4*)(cp + 4) = *(float4*)&o[4];
    }
}

// ---------------- fused GATv2 edge kernel ----------------
// grid (HEADS, B), 256 threads. All features for one (sample, head) live in smem.
// out[b,n,h*64+c] = gelu( sum_e softmax-weighted xl[src] + bo )
#define SM_STRIDE 65
#define GAT_SMEM_FLOATS (2*Nn*SM_STRIDE + Ch + Eg)
__global__ __launch_bounds__(256)
void gat_kernel(const float* __restrict__ xl, const float* __restrict__ xr,
                const float* __restrict__ att, const float* __restrict__ bo,
                const int* __restrict__ ei,
                const int* __restrict__ off, const int* __restrict__ eid,
                float* __restrict__ out)
{
    extern __shared__ float sm[];
    float* s_xl    = sm;                       // 256*65
    float* s_xr    = sm + Nn*SM_STRIDE;        // 256*65
    float* s_att   = s_xr + Nn*SM_STRIDE;      // 64
    float* s_logit = s_att + Ch;               // 8192

    const int h   = blockIdx.x;
    const int b   = blockIdx.y;
    const int tid = threadIdx.x;

    const float* xlb = xl + (size_t)b * Nn * HID + h * Ch;
    const float* xrb = xr + (size_t)b * Nn * HID + h * Ch;

    for (int i = tid; i < Nn * Ch; i += 256) {
        int n = i >> 6, c = i & 63;
        s_xl[n*SM_STRIDE + c] = xlb[(size_t)n * HID + c];
        s_xr[n*SM_STRIDE + c] = xrb[(size_t)n * HID + c];
    }
    if (tid < Ch) s_att[tid] = att[h * Ch + tid];
    __syncthreads();

    // ---- phase 1: per-edge logits ----
    const int* srcA = ei;
    const int* dstA = ei + Eg;
    for (int e = tid; e < Eg; e += 256) {
        int s = srcA[e], d = dstA[e];
        const float* pl = s_xl + s * SM_STRIDE;
        const float* pr = s_xr + d * SM_STRIDE;
        float accv = 0.f;
#pragma unroll
        for (int c = 0; c < Ch; c++) {
            float v = pl[c] + pr[c];
            v = v > 0.f ? v : NEGS * v;
            accv = fmaf(v, s_att[c], accv);
        }
        s_logit[e] = accv;
    }
    __syncthreads();

    // ---- phase 2: per-dst softmax + aggregate (warp per node) ----
    const int warp = tid >> 5, lane = tid & 31;
    for (int n = warp; n < Nn; n += 8) {
        const int o0  = off[n];
        const int deg = off[n+1] - o0;

        float m = -INFINITY;
        for (int i = lane; i < deg; i += 32) m = fmaxf(m, s_logit[eid[o0 + i]]);
#pragma unroll
        for (int d = 16; d; d >>= 1) m = fmaxf(m, __shfl_xor_sync(0xffffffffu, m, d));

        float ssum = 0.f;
        for (int i = lane; i < deg; i += 32) ssum += expf(s_logit[eid[o0 + i]] - m);
#pragma unroll
        for (int d = 16; d; d >>= 1) ssum += __shfl_xor_sync(0xffffffffu, ssum, d);
        const float inv = 1.0f / (ssum + 1e-16f);

        float a0 = 0.f, a1 = 0.f;
        for (int i = 0; i < deg; i++) {                   // fixed order: deterministic
            int e = eid[o0 + i];
            float aw = expf(s_logit[e] - m) * inv;
            int s = srcA[e];
            a0 = fmaf(aw, s_xl[s*SM_STRIDE + lane],       a0);
            a1 = fmaf(aw, s_xl[s*SM_STRIDE + 32 + lane],  a1);
        }
        float r0 = a0 + bo[h*Ch + lane];
        float r1 = a1 + bo[h*Ch + 32 + lane];
        float* op = out + (size_t)(b*Nn + n) * HID + h * Ch;
        op[lane]      = gelu_exact(r0);
        op[32 + lane] = gelu_exact(r1);
    }
}

// ---------------- mean pool over nodes ----------------
__global__ __launch_bounds__(256)
void pool_kernel(const float* __restrict__ hin, float* __restrict__ p) {
    const int b = blockIdx.x, c = threadIdx.x;
    float s = 0.f;
    const float* base = hin + (size_t)b * Nn * HID + c;
    for (int n = 0; n < Nn; n++) s += base[(size_t)n * HID];
    p[b * HID + c] = s * (1.0f / Nn);
}

// ---------------- output proj + BN + gelu ----------------
__global__ __launch_bounds__(256)
void final_kernel(const float* __restrict__ p, const float* __restrict__ W2,
                  const float* __restrict__ b2,
                  const float* __restrict__ g2, const float* __restrict__ be2,
                  const float* __restrict__ m2, const float* __restrict__ v2,
                  float* __restrict__ out) {
    const int b = blockIdx.x, c = threadIdx.x;
    __shared__ float sp[HID];
    sp[c] = p[b * HID + c];
    __syncthreads();
    float acc = 0.f;
    for (int k = 0; k < HID; k++) acc = fmaf(sp[k], W2[(size_t)k * HID + c], acc);
    acc += b2[c];
    float inv = rsqrtf(v2[c] + EPSBN);
    acc = (acc - m2[c]) * inv * g2[c] + be2[c];
    out[b * HID + c] = gelu_exact(acc);
}

// ---------------- launch ----------------
extern "C" void kernel_launch(void* const* d_in, const int* in_sizes, int n_in,
                              void* d_out, int out_size) {
    const float* x    = (const float*)d_in[0];
    const int*   ei   = (const int*)  d_in[1];
    const float* W1   = (const float*)d_in[2];
    const float* b1   = (const float*)d_in[3];
    const float* g1   = (const float*)d_in[4];
    const float* be1  = (const float*)d_in[5];
    const float* m1   = (const float*)d_in[6];
    const float* v1   = (const float*)d_in[7];
    const float* Wl0  = (const float*)d_in[8];
    const float* bl0  = (const float*)d_in[9];
    const float* Wr0  = (const float*)d_in[10];
    const float* br0  = (const float*)d_in[11];
    const float* att0 = (const float*)d_in[12];
    const float* bo0  = (const float*)d_in[13];
    const float* Wl1  = (const float*)d_in[14];
    const float* bl1  = (const float*)d_in[15];
    const float* Wr1  = (const float*)d_in[16];
    const float* br1  = (const float*)d_in[17];
    const float* att1 = (const float*)d_in[18];
    const float* bo1  = (const float*)d_in[19];
    const float* W2   = (const float*)d_in[20];
    const float* b2   = (const float*)d_in[21];
    const float* g2   = (const float*)d_in[22];
    const float* be2  = (const float*)d_in[23];
    const float* m2   = (const float*)d_in[24];
    const float* v2   = (const float*)d_in[25];

    float *h, *xl, *xr, *h2, *pl;
    int *off, *eid;
    cudaGetSymbolAddress((void**)&h,   g_h);
    cudaGetSymbolAddress((void**)&xl,  g_xl);
    cudaGetSymbolAddress((void**)&xr,  g_xr);
    cudaGetSymbolAddress((void**)&h2,  g_h2);
    cudaGetSymbolAddress((void**)&pl,  g_pool);
    cudaGetSymbolAddress((void**)&off, g_off);
    cudaGetSymbolAddress((void**)&eid, g_eid);

    const int gat_smem = GAT_SMEM_FLOATS * (int)sizeof(float);   // ~166 KB
    cudaFuncSetAttribute(gat_kernel, cudaFuncAttributeMaxDynamicSharedMemorySize, gat_smem);

    build_csr_kernel<<<1, 256>>>(ei, off, eid);

    // node_proj: h = gelu(BN(xf @ W1 + b1))
    sgemm_kernel<<<dim3(HID/128, ROWS/128), 256>>>(x, W1, ROWS, HID, F_IN,
                                                   b1, g1, be1, m1, v1, 1, h);
    // layer 0
    sgemm_kernel<<<dim3(HID/128, ROWS/128), 256>>>(h, Wl0, ROWS, HID, HID,
                                                   bl0, 0, 0, 0, 0, 0, xl);
    sgemm_kernel<<<dim3(HID/128, ROWS/128), 256>>>(h, Wr0, ROWS, HID, HID,
                                                   br0, 0, 0, 0, 0, 0, xr);
    gat_kernel<<<dim3(HEADS, Bsz), 256, gat_smem>>>(xl, xr, att0, bo0, ei, off, eid, h2);
    // layer 1
    sgemm_kernel<<<dim3(HID/128, ROWS/128), 256>>>(h2, Wl1, ROWS, HID, HID,
                                                   bl1, 0, 0, 0, 0, 0, xl);
    sgemm_kernel<<<dim3(HID/128, ROWS/128), 256>>>(h2, Wr1, ROWS, HID, HID,
                                                   br1, 0, 0, 0, 0, 0, xr);
    gat_kernel<<<dim3(HEADS, Bsz), 256, gat_smem>>>(xl, xr, att1, bo1, ei, off, eid, h);

    pool_kernel<<<Bsz, 256>>>(h, pl);
    final_kernel<<<Bsz, 256>>>(pl, W2, b2, g2, be2, m2, v2, (float*)d_out);
}

// round 2
// speedup vs baseline: 1.5684x; 1.5684x over previous
#include <cuda_runtime.h>
#include <cuda_bf16.h>
#include <math.h>

// ---------------- problem constants ----------------
#define Bsz   64
#define Nn    256
#define CT    3
#define HID   256
#define HEADS 4
#define Ch    64          // per-head channels
#define Eg    8192
#define F_IN  (Nn*CT)     // 768
#define ROWS  (Bsz*Nn)    // 16384
#define NEGS  0.2f
#define EPSBN 1e-5f

// ---------------- scratch (device globals, no allocs) ----------------
__device__ float g_h [ROWS*HID];
__device__ float g_xl[ROWS*HID];
__device__ float g_xr[ROWS*HID];
__device__ float g_h2[ROWS*HID];
__device__ float g_pool[Bsz*HID];
__device__ int   g_off[Nn+1];
__device__ int   g_eid[Eg];

__device__ __forceinline__ float gelu_exact(float x) {
    return x * normcdff(x);
}

// ---------------- deterministic CSR build: single-block counting sort ----------------
// 256 threads = 8 warps. Each warp owns a contiguous 1024-edge chunk.
// Per-warp histogram + within-warp stable ranks via match_any -> fully
// deterministic CSR ordered by edge index.
__global__ __launch_bounds__(256)
void build_csr_kernel(const int* __restrict__ ei,
                      int* __restrict__ off, int* __restrict__ eid) {
    __shared__ int hist[8][Nn];     // per-warp counts -> exclusive warp prefix
    __shared__ int s_loc[Eg];       // within-warp rank for each edge
    __shared__ int s_off[Nn+1];

    const int tid  = threadIdx.x;
    const int w    = tid >> 5;
    const int lane = tid & 31;
    const int* dst = ei + Eg;

    for (int i = tid; i < 8 * Nn; i += 256) ((int*)hist)[i] = 0;
    __syncthreads();

    // pass 1: per-warp counts and per-edge within-warp ranks (stable in e order)
    const int base = w * 1024;
#pragma unroll 1
    for (int g = 0; g < 32; g++) {
        const int e = base + g * 32 + lane;
        const int d = dst[e];
        unsigned mask = __match_any_sync(0xffffffffu, d);
        int leader = __ffs(mask) - 1;
        int rank   = __popc(mask & ((1u << lane) - 1u));
        int cur    = hist[w][d];          // same-d lanes read identical value
        s_loc[e]   = cur + rank;
        __syncwarp();
        if (lane == leader) hist[w][d] = cur + __popc(mask);
        __syncwarp();
    }
    __syncthreads();

    // exclusive prefix across warps per node; node totals
    __shared__ int tot[Nn];
    if (tid < Nn) {
        int run = 0;
#pragma unroll
        for (int ww = 0; ww < 8; ww++) {
            int c = hist[ww][tid];
            hist[ww][tid] = run;
            run += c;
        }
        tot[tid] = run;
    }
    __syncthreads();
    if (tid == 0) {
        int run = 0;
        for (int n = 0; n < Nn; n++) { s_off[n] = run; run += tot[n]; }
        s_off[Nn] = run;
    }
    __syncthreads();

    if (tid < Nn) off[tid] = s_off[tid];
    if (tid == 0) off[Nn] = s_off[Nn];

    // pass 2: scatter
    for (int e = tid; e < Eg; e += 256) {
        const int d  = dst[e];
        const int we = e >> 10;
        eid[s_off[d] + hist[we][d] + s_loc[e]] = e;
    }
}

// ---------------- SGEMM with optional dual-B output ----------------
// C[M,N] = A[M,K] @ B[K,N] (+bias) (+BN+gelu). 128x128x8 tile, 256 thr, 8x8 micro.
// If dual != 0: grid.x = 2*(N/128); blocks with bx >= N/128 compute A@B2 -> C2.
__global__ __launch_bounds__(256)
void sgemm_kernel(const float* __restrict__ A,
                  const float* __restrict__ B,  const float* __restrict__ bias,  float* __restrict__ C,
                  const float* __restrict__ B2, const float* __restrict__ bias2, float* __restrict__ C2,
                  int M, int N, int K,
                  const float* __restrict__ gam, const float* __restrict__ bet,
                  const float* __restrict__ mu,  const float* __restrict__ var,
                  int epi, int dual)
{
    __shared__ float As[8][128];
    __shared__ float Bs[8][128];

    const int tid = threadIdx.x;
    int bx = blockIdx.x;
    const int nblk = dual ? (gridDim.x >> 1) : gridDim.x;
    if (dual && bx >= nblk) {
        bx -= nblk;
        B = B2; bias = bias2; C = C2;
    }
    const int cb  = bx * 128;
    const int rb  = blockIdx.y * 128;

    const int ar  = tid >> 1;
    const int ac  = (tid & 1) * 4;
    const int br  = tid >> 5;
    const int bc  = (tid & 31) * 4;
    const int tx  = tid & 15;
    const int ty  = tid >> 4;

    float acc[8][8];
#pragma unroll
    for (int i = 0; i < 8; i++)
#pragma unroll
        for (int j = 0; j < 8; j++) acc[i][j] = 0.f;

    const float* Ap = A + (size_t)(rb + ar) * K + ac;
    const float* Bp = B + (size_t)br * N + cb + bc;

    float4 av = *(const float4*)(Ap);
    float4 bv = *(const float4*)(Bp);

    for (int kt = 0; kt < K; kt += 8) {
        As[ac+0][ar] = av.x; As[ac+1][ar] = av.y;
        As[ac+2][ar] = av.z; As[ac+3][ar] = av.w;
        *(float4*)&Bs[br][bc] = bv;
        __syncthreads();
        if (kt + 8 < K) {
            av = *(const float4*)(Ap + kt + 8);
            bv = *(const float4*)(Bp + (size_t)(kt + 8) * N);
        }
#pragma unroll
        for (int kk = 0; kk < 8; kk++) {
            float a[8], b[8];
            *(float4*)&a[0] = *(const float4*)&As[kk][ty*8];
            *(float4*)&a[4] = *(const float4*)&As[kk][ty*8+4];
            *(float4*)&b[0] = *(const float4*)&Bs[kk][tx*8];
            *(float4*)&b[4] = *(const float4*)&Bs[kk][tx*8+4];
#pragma unroll
            for (int i = 0; i < 8; i++)
#pragma unroll
                for (int j = 0; j < 8; j++) acc[i][j] = fmaf(a[i], b[j], acc[i][j]);
        }
        __syncthreads();
    }

    const int row0 = rb + ty * 8;
    const int col0 = cb + tx * 8;
    float pb[8], pscale[8], pshift[8];
#pragma unroll
    for (int j = 0; j < 8; j++) pb[j] = bias[col0 + j];
    if (epi == 1) {
#pragma unroll
        for (int j = 0; j < 8; j++) {
            float inv = rsqrtf(var[col0 + j] + EPSBN);
            pscale[j] = gam[col0 + j] * inv;
            pshift[j] = bet[col0 + j] - mu[col0 + j] * pscale[j];
        }
    }
#pragma unroll
    for (int i = 0; i < 8; i++) {
        float o[8];
#pragma unroll
        for (int j = 0; j < 8; j++) {
            float v = acc[i][j] + pb[j];
            if (epi == 1) {
                v = v * pscale[j] + pshift[j];
                v = gelu_exact(v);
            }
            o[j] = v;
        }
        float* cp = C + (size_t)(row0 + i) * N + col0;
        *(float4*)(cp)     = *(float4*)&o[0];
        *(float4*)(cp + 4) = *(float4*)&o[4];
    }
}

// ---------------- fused GATv2 edge kernel ----------------
// grid (HEADS, B), 512 threads. All per-(sample,head) features in smem.
#define SM_STRIDE 65
// layout: s_xl[256*65] | s_xr[256*65] | s_att[64] | s_logit[8192] | s_off[258]
// after phase 1, s_xr region is reused as: s_esrc[8192] (int) + s_elog[8192] (float)
#define GAT_SMEM_FLOATS (2*Nn*SM_STRIDE + 64 + Eg + (Nn+2))
__global__ __launch_bounds__(512)
void gat_kernel(const float* __restrict__ xl, const float* __restrict__ xr,
                const float* __restrict__ att, const float* __restrict__ bo,
                const int* __restrict__ ei,
                const int* __restrict__ off, const int* __restrict__ eid,
                float* __restrict__ out)
{
    extern __shared__ float sm[];
    float* s_xl    = sm;                            // 256*65
    float* s_xr    = sm + Nn*SM_STRIDE;             // 256*65 (reused later)
    float* s_att   = sm + 2*Nn*SM_STRIDE;           // 64
    float* s_logit = s_att + 64;                    // 8192
    int*   s_off   = (int*)(s_logit + Eg);          // 257
    // phase>=2 aliases into s_xr region:
    int*   s_esrc  = (int*)s_xr;                    // 8192
    float* s_elog  = s_xr + Eg;                     // 8192 (fits: 2*8192 <= 256*65)

    const int h   = blockIdx.x;
    const int b   = blockIdx.y;
    const int tid = threadIdx.x;
    const int nthr = 512;

    const float* xlb = xl + (size_t)b * Nn * HID + h * Ch;
    const float* xrb = xr + (size_t)b * Nn * HID + h * Ch;

    for (int i = tid; i < Nn * Ch; i += nthr) {
        int n = i >> 6, c = i & 63;
        s_xl[n*SM_STRIDE + c] = xlb[(size_t)n * HID + c];
        s_xr[n*SM_STRIDE + c] = xrb[(size_t)n * HID + c];
    }
    if (tid < Ch) s_att[tid] = att[h * Ch + tid];
    if (tid >= nthr - (Nn+1) && tid < nthr) {
        int k = tid - (nthr - (Nn+1));
        s_off[k] = off[k];
    }
    __syncthreads();

    // ---- phase 1: per-edge logits (thread per edge) ----
    const int* srcA = ei;
    const int* dstA = ei + Eg;
    for (int e = tid; e < Eg; e += nthr) {
        int s = srcA[e], d = dstA[e];
        const float* pl = s_xl + s * SM_STRIDE;
        const float* pr = s_xr + d * SM_STRIDE;
        float accv = 0.f;
#pragma unroll
        for (int c = 0; c < Ch; c++) {
            float v = pl[c] + pr[c];
            v = v > 0.f ? v : NEGS * v;
            accv = fmaf(v, s_att[c], accv);
        }
        s_logit[e] = accv;
    }
    __syncthreads();

    // ---- phase 1.5: build CSR-ordered (src, logit) arrays (overwrites s_xr) ----
    for (int i = tid; i < Eg; i += nthr) {
        int e = eid[i];
        s_esrc[i] = srcA[e];
        s_elog[i] = s_logit[e];
    }
    __syncthreads();

    // ---- phase 2: per-dst softmax + aggregate (warp per node, 16 warps) ----
    const int warp = tid >> 5, lane = tid & 31;
    const float bo0 = bo[h*Ch + lane];
    const float bo1 = bo[h*Ch + 32 + lane];
    for (int n = warp; n < Nn; n += 16) {
        const int o0  = s_off[n];
        const int deg = s_off[n+1] - o0;

        float m = -INFINITY;
        for (int i = lane; i < deg; i += 32) m = fmaxf(m, s_elog[o0 + i]);
#pragma unroll
        for (int d = 16; d; d >>= 1) m = fmaxf(m, __shfl_xor_sync(0xffffffffu, m, d));

        float ssum = 0.f;
        for (int i = lane; i < deg; i += 32) ssum += expf(s_elog[o0 + i] - m);
#pragma unroll
        for (int d = 16; d; d >>= 1) ssum += __shfl_xor_sync(0xffffffffu, ssum, d);
        const float inv = 1.0f / (ssum + 1e-16f);

        // pre-normalize weights in place (this warp owns [o0, o0+deg))
        for (int i = lane; i < deg; i += 32)
            s_elog[o0 + i] = expf(s_elog[o0 + i] - m) * inv;
        __syncwarp();

        float a0 = 0.f, a1 = 0.f;
        for (int i = 0; i < deg; i++) {           // CSR order: deterministic
            float aw = s_elog[o0 + i];            // broadcast LDS
            int   s  = s_esrc[o0 + i];            // broadcast LDS
            a0 = fmaf(aw, s_xl[s*SM_STRIDE + lane],      a0);
            a1 = fmaf(aw, s_xl[s*SM_STRIDE + 32 + lane], a1);
        }
        float* op = out + (size_t)(b*Nn + n) * HID + h * Ch;
        op[lane]      = gelu_exact(a0 + bo0);
        op[32 + lane] = gelu_exact(a1 + bo1);
    }
}

// ---------------- mean pool over nodes ----------------
__global__ __launch_bounds__(256)
void pool_kernel(const float* __restrict__ hin, float* __restrict__ p) {
    const int b = blockIdx.x, c = threadIdx.x;
    float s = 0.f;
    const float* base = hin + (size_t)b * Nn * HID + c;
    for (int n = 0; n < Nn; n++) s += base[(size_t)n * HID];
    p[b * HID + c] = s * (1.0f / Nn);
}

// ---------------- output proj + BN + gelu ----------------
__global__ __launch_bounds__(256)
void final_kernel(const float* __restrict__ p, const float* __restrict__ W2,
                  const float* __restrict__ b2,
                  const float* __restrict__ g2, const float* __restrict__ be2,
                  const float* __restrict__ m2, const float* __restrict__ v2,
                  float* __restrict__ out) {
    const int b = blockIdx.x, c = threadIdx.x;
    __shared__ float sp[HID];
    sp[c] = p[b * HID + c];
    __syncthreads();
    float acc = 0.f;
    for (int k = 0; k < HID; k++) acc = fmaf(sp[k], W2[(size_t)k * HID + c], acc);
    acc += b2[c];
    float inv = rsqrtf(v2[c] + EPSBN);
    acc = (acc - m2[c]) * inv * g2[c] + be2[c];
    out[b * HID + c] = gelu_exact(acc);
}

// ---------------- launch ----------------
extern "C" void kernel_launch(void* const* d_in, const int* in_sizes, int n_in,
                              void* d_out, int out_size) {
    const float* x    = (const float*)d_in[0];
    const int*   ei   = (const int*)  d_in[1];
    const float* W1   = (const float*)d_in[2];
    const float* b1   = (const float*)d_in[3];
    const float* g1   = (const float*)d_in[4];
    const float* be1  = (const float*)d_in[5];
    const float* m1   = (const float*)d_in[6];
    const float* v1   = (const float*)d_in[7];
    const float* Wl0  = (const float*)d_in[8];
    const float* bl0  = (const float*)d_in[9];
    const float* Wr0  = (const float*)d_in[10];
    const float* br0  = (const float*)d_in[11];
    const float* att0 = (const float*)d_in[12];
    const float* bo0  = (const float*)d_in[13];
    const float* Wl1  = (const float*)d_in[14];
    const float* bl1  = (const float*)d_in[15];
    const float* Wr1  = (const float*)d_in[16];
    const float* br1  = (const float*)d_in[17];
    const float* att1 = (const float*)d_in[18];
    const float* bo1  = (const float*)d_in[19];
    const float* W2   = (const float*)d_in[20];
    const float* b2   = (const float*)d_in[21];
    const float* g2   = (const float*)d_in[22];
    const float* be2  = (const float*)d_in[23];
    const float* m2   = (const float*)d_in[24];
    const float* v2   = (const float*)d_in[25];

    float *h, *xl, *xr, *h2, *pl;
    int *off, *eid;
    cudaGetSymbolAddress((void**)&h,   g_h);
    cudaGetSymbolAddress((void**)&xl,  g_xl);
    cudaGetSymbolAddress((void**)&xr,  g_xr);
    cudaGetSymbolAddress((void**)&h2,  g_h2);
    cudaGetSymbolAddress((void**)&pl,  g_pool);
    cudaGetSymbolAddress((void**)&off, g_off);
    cudaGetSymbolAddress((void**)&eid, g_eid);

    const int gat_smem = GAT_SMEM_FLOATS * (int)sizeof(float);
    cudaFuncSetAttribute(gat_kernel, cudaFuncAttributeMaxDynamicSharedMemorySize, gat_smem);

    build_csr_kernel<<<1, 256>>>(ei, off, eid);

    // node_proj: h = gelu(BN(x @ W1 + b1))
    sgemm_kernel<<<dim3(HID/128, ROWS/128), 256>>>(x, W1, b1, h,
                                                   0, 0, 0,
                                                   ROWS, HID, F_IN,
                                                   g1, be1, m1, v1, 1, 0);
    // layer 0: xl = h@Wl0+bl0, xr = h@Wr0+br0 in one launch
    sgemm_kernel<<<dim3(2*HID/128, ROWS/128), 256>>>(h, Wl0, bl0, xl,
                                                     Wr0, br0, xr,
                                                     ROWS, HID, HID,
                                                     0, 0, 0, 0, 0, 1);
    gat_kernel<<<dim3(HEADS, Bsz), 512, gat_smem>>>(xl, xr, att0, bo0, ei, off, eid, h2);
    // layer 1
    sgemm_kernel<<<dim3(2*HID/128, ROWS/128), 256>>>(h2, Wl1, bl1, xl,
                                                     Wr1, br1, xr,
                                                     ROWS, HID, HID,
                                                     0, 0, 0, 0, 0, 1);
    gat_kernel<<<dim3(HEADS, Bsz), 512, gat_smem>>>(xl, xr, att1, bo1, ei, off, eid, h);

    pool_kernel<<<Bsz, 256>>>(h, pl);
    final_kernel<<<Bsz, 256>>>(pl, W2, b2, g2, be2, m2, v2, (float*)d_out);
}

// round 3
// speedup vs baseline: 1.8289x; 1.1661x over previous
#include <cuda_runtime.h>
#include <cuda_bf16.h>
#include <math.h>

// ---------------- problem constants ----------------
#define Bsz   64
#define Nn    256
#define CT    3
#define HID   256
#define HEADS 4
#define Ch    64
#define Eg    8192
#define F_IN  (Nn*CT)
#define ROWS  (Bsz*Nn)
#define NEGS  0.2f
#define EPSBN 1e-5f

// ---------------- scratch ----------------
__device__ float g_h [ROWS*HID];
__device__ float g_xl[ROWS*HID];
__device__ float g_xr[ROWS*HID];
__device__ float g_h2[ROWS*HID];
__device__ float g_pool[Bsz*HID];
__device__ int   g_off[Nn+1];
__device__ int   g_srce[Eg];   // CSR-ordered source node ids
__device__ int   g_dste[Eg];   // CSR-ordered dest node ids

__device__ __forceinline__ float gelu_exact(float x) { return x * normcdff(x); }

// ---------------- deterministic CSR build ----------------
__global__ __launch_bounds__(256)
void build_csr_kernel(const int* __restrict__ ei,
                      int* __restrict__ off,
                      int* __restrict__ srce, int* __restrict__ dste) {
    __shared__ int hist[8][Nn];
    __shared__ int s_loc[Eg];
    __shared__ int s_off[Nn+1];

    const int tid  = threadIdx.x;
    const int w    = tid >> 5;
    const int lane = tid & 31;
    const int* srcA = ei;
    const int* dstA = ei + Eg;

    for (int i = tid; i < 8 * Nn; i += 256) ((int*)hist)[i] = 0;
    __syncthreads();

    const int base = w * 1024;
#pragma unroll 1
    for (int g = 0; g < 32; g++) {
        const int e = base + g * 32 + lane;
        const int d = dstA[e];
        unsigned mask = __match_any_sync(0xffffffffu, d);
        int leader = __ffs(mask) - 1;
        int rank   = __popc(mask & ((1u << lane) - 1u));
        int cur    = hist[w][d];
        s_loc[e]   = cur + rank;
        __syncwarp();
        if (lane == leader) hist[w][d] = cur + __popc(mask);
        __syncwarp();
    }
    __syncthreads();

    __shared__ int tot[Nn];
    if (tid < Nn) {
        int run = 0;
#pragma unroll
        for (int ww = 0; ww < 8; ww++) {
            int c = hist[ww][tid];
            hist[ww][tid] = run;
            run += c;
        }
        tot[tid] = run;
    }
    __syncthreads();
    if (tid == 0) {
        int run = 0;
        for (int n = 0; n < Nn; n++) { s_off[n] = run; run += tot[n]; }
        s_off[Nn] = run;
    }
    __syncthreads();

    if (tid < Nn) off[tid] = s_off[tid];
    if (tid == 0) off[Nn] = s_off[Nn];

    for (int e = tid; e < Eg; e += 256) {
        const int d  = dstA[e];
        const int we = e >> 10;
        const int pos = s_off[d] + hist[we][d] + s_loc[e];
        srce[pos] = srcA[e];
        dste[pos] = d;
    }
}

// ---------------- double-buffered SGEMM (dual-output capable) ----------------
__global__ __launch_bounds__(256)
void sgemm_kernel(const float* __restrict__ A,
                  const float* __restrict__ B,  const float* __restrict__ bias,  float* __restrict__ C,
                  const float* __restrict__ B2, const float* __restrict__ bias2, float* __restrict__ C2,
                  int M, int N, int K,
                  const float* __restrict__ gam, const float* __restrict__ bet,
                  const float* __restrict__ mu,  const float* __restrict__ var,
                  int epi, int dual)
{
    __shared__ float As[2][8][128];
    __shared__ float Bs[2][8][128];

    const int tid = threadIdx.x;
    int bx = blockIdx.x;
    const int nblk = dual ? (gridDim.x >> 1) : gridDim.x;
    if (dual && bx >= nblk) {
        bx -= nblk;
        B = B2; bias = bias2; C = C2;
    }
    const int cb  = bx * 128;
    const int rb  = blockIdx.y * 128;

    const int ar  = tid >> 1;
    const int ac  = (tid & 1) * 4;
    const int br  = tid >> 5;
    const int bc  = (tid & 31) * 4;
    const int tx  = tid & 15;
    const int ty  = tid >> 4;

    float acc[8][8];
#pragma unroll
    for (int i = 0; i < 8; i++)
#pragma unroll
        for (int j = 0; j < 8; j++) acc[i][j] = 0.f;

    const float* Ap = A + (size_t)(rb + ar) * K + ac;
    const float* Bp = B + (size_t)br * N + cb + bc;

    float4 av = *(const float4*)(Ap);
    float4 bv = *(const float4*)(Bp);
    As[0][ac+0][ar] = av.x; As[0][ac+1][ar] = av.y;
    As[0][ac+2][ar] = av.z; As[0][ac+3][ar] = av.w;
    *(float4*)&Bs[0][br][bc] = bv;
    __syncthreads();

    int buf = 0;
    for (int kt = 0; kt < K; kt += 8) {
        const bool has = (kt + 8) < K;
        if (has) {
            av = *(const float4*)(Ap + kt + 8);
            bv = *(const float4*)(Bp + (size_t)(kt + 8) * N);
        }
#pragma unroll
        for (int kk = 0; kk < 8; kk++) {
            float a[8], b[8];
            *(float4*)&a[0] = *(const float4*)&As[buf][kk][ty*8];
            *(float4*)&a[4] = *(const float4*)&As[buf][kk][ty*8+4];
            *(float4*)&b[0] = *(const float4*)&Bs[buf][kk][tx*8];
            *(float4*)&b[4] = *(const float4*)&Bs[buf][kk][tx*8+4];
#pragma unroll
            for (int i = 0; i < 8; i++)
#pragma unroll
                for (int j = 0; j < 8; j++) acc[i][j] = fmaf(a[i], b[j], acc[i][j]);
        }
        if (has) {
            const int nb = buf ^ 1;
            As[nb][ac+0][ar] = av.x; As[nb][ac+1][ar] = av.y;
            As[nb][ac+2][ar] = av.z; As[nb][ac+3][ar] = av.w;
            *(float4*)&Bs[nb][br][bc] = bv;
            __syncthreads();
            buf = nb;
        }
    }

    const int row0 = rb + ty * 8;
    const int col0 = cb + tx * 8;
    float pb[8], pscale[8], pshift[8];
#pragma unroll
    for (int j = 0; j < 8; j++) pb[j] = bias[col0 + j];
    if (epi == 1) {
#pragma unroll
        for (int j = 0; j < 8; j++) {
            float inv = rsqrtf(var[col0 + j] + EPSBN);
            pscale[j] = gam[col0 + j] * inv;
            pshift[j] = bet[col0 + j] - mu[col0 + j] * pscale[j];
        }
    }
#pragma unroll
    for (int i = 0; i < 8; i++) {
        float o[8];
#pragma unroll
        for (int j = 0; j < 8; j++) {
            float v = acc[i][j] + pb[j];
            if (epi == 1) {
                v = v * pscale[j] + pshift[j];
                v = gelu_exact(v);
            }
            o[j] = v;
        }
        float* cp = C + (size_t)(row0 + i) * N + col0;
        *(float4*)(cp)     = *(float4*)&o[0];
        *(float4*)(cp + 4) = *(float4*)&o[4];
    }
}

// ---------------- fused GATv2 edge kernel ----------------
// grid (HEADS, B), 512 threads, one (sample,head) per block, all data in smem.
#define SM_STRIDE 68   // 16B-aligned rows -> float4 LDS; 17*4 stride keeps banks spread
// floats: s_xl[256*68] | s_xr[256*68] | s_att[64] | s_pair[2*8192] | s_off[257]
#define GAT_SMEM_FLOATS (2*Nn*SM_STRIDE + 64 + 2*Eg + (Nn+1))
__global__ __launch_bounds__(512)
void gat_kernel(const float* __restrict__ xl, const float* __restrict__ xr,
                const float* __restrict__ att, const float* __restrict__ bo,
                const int* __restrict__ srce, const int* __restrict__ dste,
                const int* __restrict__ off,
                float* __restrict__ out)
{
    extern __shared__ float sm[];
    float*  s_xl   = sm;                              // 256*68
    float*  s_xr   = sm + Nn*SM_STRIDE;               // 256*68
    float*  s_att  = sm + 2*Nn*SM_STRIDE;             // 64
    float2* s_pair = (float2*)(s_att + 64);           // 8192 x (logit/w, srcoff)
    int*    s_off  = (int*)(s_att + 64 + 2*Eg);       // 257

    const int h    = blockIdx.x;
    const int b    = blockIdx.y;
    const int tid  = threadIdx.x;
    const int nthr = 512;

    const float* xlb = xl + (size_t)b * Nn * HID + h * Ch;
    const float* xrb = xr + (size_t)b * Nn * HID + h * Ch;

    // stage features (float4 global loads, float4 smem stores)
    for (int i = tid; i < Nn * (Ch/4); i += nthr) {
        int n = i >> 4, c4 = i & 15;
        float4 lv = *(const float4*)(xlb + (size_t)n * HID + 4*c4);
        float4 rv = *(const float4*)(xrb + (size_t)n * HID + 4*c4);
        *(float4*)&s_xl[n*SM_STRIDE + 4*c4] = lv;
        *(float4*)&s_xr[n*SM_STRIDE + 4*c4] = rv;
    }
    if (tid < Ch) s_att[tid] = att[h * Ch + tid];
    if (tid >= nthr - (Nn+1)) s_off[tid - (nthr - (Nn+1))] = off[tid - (nthr - (Nn+1))];
    __syncthreads();

    // ---- phase 1: logits in CSR order ----
    for (int i = tid; i < Eg; i += nthr) {
        const int s = srce[i];                 // coalesced
        const int d = dste[i];                 // coalesced, ~uniform within warp
        const float4* pl = (const float4*)&s_xl[s * SM_STRIDE];
        const float4* pr = (const float4*)&s_xr[d * SM_STRIDE];
        float accv = 0.f;
#pragma unroll
        for (int c4 = 0; c4 < 16; c4++) {
            const float4 a4 = *(const float4*)&s_att[4*c4];
            const float4 l4 = pl[c4];
            const float4 r4 = pr[c4];
            float v;
            v = l4.x + r4.x; v = v > 0.f ? v : NEGS * v; accv = fmaf(v, a4.x, accv);
            v = l4.y + r4.y; v = v > 0.f ? v : NEGS * v; accv = fmaf(v, a4.y, accv);
            v = l4.z + r4.z; v = v > 0.f ? v : NEGS * v; accv = fmaf(v, a4.z, accv);
            v = l4.w + r4.w; v = v > 0.f ? v : NEGS * v; accv = fmaf(v, a4.w, accv);
        }
        s_pair[i] = make_float2(accv, __int_as_float(s * SM_STRIDE));
    }
    __syncthreads();

    // ---- phase 2: warp per node; half-warp per edge, float4 channels ----
    const int warp = tid >> 5, lane = tid & 31;
    const int cg = lane & 15;      // channel group (4 floats)
    const int ep = lane >> 4;      // edge parity within pair
    const float4 bo4 = *(const float4*)(bo + h*Ch + 4*cg);

    for (int n = warp; n < Nn; n += 16) {
        const int o0  = s_off[n];
        const int deg = s_off[n+1] - o0;

        float m = -INFINITY;
        for (int i = lane; i < deg; i += 32) m = fmaxf(m, s_pair[o0 + i].x);
#pragma unroll
        for (int d = 16; d; d >>= 1) m = fmaxf(m, __shfl_xor_sync(0xffffffffu, m, d));

        float ssum = 0.f;
        for (int i = lane; i < deg; i += 32) ssum += expf(s_pair[o0 + i].x - m);
#pragma unroll
        for (int d = 16; d; d >>= 1) ssum += __shfl_xor_sync(0xffffffffu, ssum, d);
        const float inv = 1.0f / (ssum + 1e-16f);

        for (int i = lane; i < deg; i += 32)
            s_pair[o0 + i].x = expf(s_pair[o0 + i].x - m) * inv;
        __syncwarp();

        float4 acc = make_float4(0.f, 0.f, 0.f, 0.f);
#pragma unroll 4
        for (int j = ep; j < deg; j += 2) {
            const float2 p = s_pair[o0 + j];            // 8B broadcast per half-warp
            const int soff = __float_as_int(p.y);
            const float4 xv = *(const float4*)&s_xl[soff + 4*cg];
            acc.x = fmaf(p.x, xv.x, acc.x);
            acc.y = fmaf(p.x, xv.y, acc.y);
            acc.z = fmaf(p.x, xv.z, acc.z);
            acc.w = fmaf(p.x, xv.w, acc.w);
        }
        acc.x += __shfl_down_sync(0xffffffffu, acc.x, 16);
        acc.y += __shfl_down_sync(0xffffffffu, acc.y, 16);
        acc.z += __shfl_down_sync(0xffffffffu, acc.z, 16);
        acc.w += __shfl_down_sync(0xffffffffu, acc.w, 16);

        if (ep == 0) {
            float4 r;
            r.x = gelu_exact(acc.x + bo4.x);
            r.y = gelu_exact(acc.y + bo4.y);
            r.z = gelu_exact(acc.z + bo4.z);
            r.w = gelu_exact(acc.w + bo4.w);
            *(float4*)(out + (size_t)(b*Nn + n) * HID + h*Ch + 4*cg) = r;
        }
    }
}

// ---------------- mean pool over nodes ----------------
__global__ __launch_bounds__(256)
void pool_kernel(const float* __restrict__ hin, float* __restrict__ p) {
    const int b = blockIdx.x, c = threadIdx.x;
    float s = 0.f;
    const float* base = hin + (size_t)b * Nn * HID + c;
    for (int n = 0; n < Nn; n++) s += base[(size_t)n * HID];
    p[b * HID + c] = s * (1.0f / Nn);
}

// ---------------- output proj + BN + gelu ----------------
__global__ __launch_bounds__(256)
void final_kernel(const float* __restrict__ p, const float* __restrict__ W2,
                  const float* __restrict__ b2,
                  const float* __restrict__ g2, const float* __restrict__ be2,
                  const float* __restrict__ m2, const float* __restrict__ v2,
                  float* __restrict__ out) {
    const int b = blockIdx.x, c = threadIdx.x;
    __shared__ float sp[HID];
    sp[c] = p[b * HID + c];
    __syncthreads();
    float acc = 0.f;
    for (int k = 0; k < HID; k++) acc = fmaf(sp[k], W2[(size_t)k * HID + c], acc);
    acc += b2[c];
    float inv = rsqrtf(v2[c] + EPSBN);
    acc = (acc - m2[c]) * inv * g2[c] + be2[c];
    out[b * HID + c] = gelu_exact(acc);
}

// ---------------- launch ----------------
extern "C" void kernel_launch(void* const* d_in, const int* in_sizes, int n_in,
                              void* d_out, int out_size) {
    const float* x    = (const float*)d_in[0];
    const int*   ei   = (const int*)  d_in[1];
    const float* W1   = (const float*)d_in[2];
    const float* b1   = (const float*)d_in[3];
    const float* g1   = (const float*)d_in[4];
    const float* be1  = (const float*)d_in[5];
    const float* m1   = (const float*)d_in[6];
    const float* v1   = (const float*)d_in[7];
    const float* Wl0  = (const float*)d_in[8];
    const float* bl0  = (const float*)d_in[9];
    const float* Wr0  = (const float*)d_in[10];
    const float* br0  = (const float*)d_in[11];
    const float* att0 = (const float*)d_in[12];
    const float* bo0  = (const float*)d_in[13];
    const float* Wl1  = (const float*)d_in[14];
    const float* bl1  = (const float*)d_in[15];
    const float* Wr1  = (const float*)d_in[16];
    const float* br1  = (const float*)d_in[17];
    const float* att1 = (const float*)d_in[18];
    const float* bo1  = (const float*)d_in[19];
    const float* W2   = (const float*)d_in[20];
    const float* b2   = (const float*)d_in[21];
    const float* g2   = (const float*)d_in[22];
    const float* be2  = (const float*)d_in[23];
    const float* m2   = (const float*)d_in[24];
    const float* v2   = (const float*)d_in[25];

    float *h, *xl, *xr, *h2, *pl;
    int *off, *srce, *dste;
    cudaGetSymbolAddress((void**)&h,    g_h);
    cudaGetSymbolAddress((void**)&xl,   g_xl);
    cudaGetSymbolAddress((void**)&xr,   g_xr);
    cudaGetSymbolAddress((void**)&h2,   g_h2);
    cudaGetSymbolAddress((void**)&pl,   g_pool);
    cudaGetSymbolAddress((void**)&off,  g_off);
    cudaGetSymbolAddress((void**)&srce, g_srce);
    cudaGetSymbolAddress((void**)&dste, g_dste);

    const int gat_smem = GAT_SMEM_FLOATS * (int)sizeof(float);   // ~206 KB
    cudaFuncSetAttribute(gat_kernel, cudaFuncAttributeMaxDynamicSharedMemorySize, gat_smem);

    build_csr_kernel<<<1, 256>>>(ei, off, srce, dste);

    sgemm_kernel<<<dim3(HID/128, ROWS/128), 256>>>(x, W1, b1, h,
                                                   0, 0, 0,
                                                   ROWS, HID, F_IN,
                                                   g1, be1, m1, v1, 1, 0);
    sgemm_kernel<<<dim3(2*HID/128, ROWS/128), 256>>>(h, Wl0, bl0, xl,
                                                     Wr0, br0, xr,
                                                     ROWS, HID, HID,
                                                     0, 0, 0, 0, 0, 1);
    gat_kernel<<<dim3(HEADS, Bsz), 512, gat_smem>>>(xl, xr, att0, bo0, srce, dste, off, h2);
    sgemm_kernel<<<dim3(2*HID/128, ROWS/128), 256>>>(h2, Wl1, bl1, xl,
                                                     Wr1, br1, xr,
                                                     ROWS, HID, HID,
                                                     0, 0, 0, 0, 0, 1);
    gat_kernel<<<dim3(HEADS, Bsz), 512, gat_smem>>>(xl, xr, att1, bo1, srce, dste, off, h);

    pool_kernel<<<Bsz, 256>>>(h, pl);
    final_kernel<<<Bsz, 256>>>(pl, W2, b2, g2, be2, m2, v2, (float*)d_out);
}